// round 16
// baseline (speedup 1.0000x reference)
#include <cuda_runtime.h>

#define L_DIM 512
#define B_DIM 64
#define H_DIM 1024
#define K2_GRID 296   // 2 blocks per SM on 148 SMs

// Scratch (no allocations allowed)
__device__ __align__(16) float g_u_part[4 * H_DIM];   // 4 k-quarter partials
__device__ float g_attn[B_DIM * L_DIM];

// ---------------------------------------------------------------------------
// K1: partial u, vectorized. Grid (32 h-groups, 4 k-quarters) = 128 blocks
// x 1024 thr. Block (hg,kq): h-cols [hg*32,+32), k-rows [kq*256,+256).
// Thread t: hl4 = t&7 (h-quad), kg = t>>3 (128 k-groups, 2 rows each).
// W loads are LDG.128 (float4) issued before the smem sync; vec is staged
// through smem (256 loads/block instead of 8192). 16KB smem reduce,
// conflict-free both phases. Atomic-free, fence-free.
// ---------------------------------------------------------------------------
__global__ void __launch_bounds__(1024) compute_u_kernel(const float* __restrict__ W_att,
                                                         const float* __restrict__ vec) {
    __shared__ float sv[256];
    __shared__ float red[128 * 32];           // 16 KB
    const int t   = threadIdx.x;
    const int hl4 = t & 7;                    // h-quad within block
    const int kg  = t >> 3;                   // 0..127
    const int h   = blockIdx.x * 32 + hl4 * 4;
    const int k0  = blockIdx.y * 256;

    // Issue both W row loads immediately (in flight across the sync).
    const float* wp = W_att + (size_t)(k0 + kg) * (2 * H_DIM) + H_DIM + h;
    const float4 w0 = *reinterpret_cast<const float4*>(wp);
    const float4 w1 = *reinterpret_cast<const float4*>(wp + (size_t)128 * (2 * H_DIM));

    if (t < 256) sv[t] = vec[k0 + t];
    __syncthreads();

    const float vk0 = sv[kg];
    const float vk1 = sv[kg + 128];

    float4 a;
    a.x = w0.x * vk0 + w1.x * vk1;
    a.y = w0.y * vk0 + w1.y * vk1;
    a.z = w0.z * vk0 + w1.z * vk1;
    a.w = w0.w * vk0 + w1.w * vk1;
    reinterpret_cast<float4*>(red)[kg * 8 + hl4] = a;
    __syncthreads();

    if (t < 32) {                             // thread t owns h-col (t)
        float s = 0.f;
        #pragma unroll 8
        for (int g = 0; g < 128; g++) s += red[g * 32 + t];  // bank = t: conflict-free
        g_u_part[blockIdx.y * H_DIM + blockIdx.x * 32 + t] = s;
    }
}

// ---------------------------------------------------------------------------
// K2: attn[b,l] = <hs_encoder[l,b,:], u>   (the 134 MB streaming kernel)
// PERSISTENT: 296 blocks x 512 thr; staging (sum of 4 k-partials) happens
// once per block (296 x 16KB = 4.7MB L2), then each warp grid-strides over
// rows (~7 per warp). Hot loop: __ldcs float4 (evict-first), MLP=8 per row
// plus cross-iteration ILP. NO fences, NO atomics.
// ---------------------------------------------------------------------------
__global__ void __launch_bounds__(512) dot_kernel(const float* __restrict__ hs) {
    __shared__ float4 su[H_DIM / 4];          // 4 KB
    const int t = threadIdx.x;
    if (t < H_DIM / 4) {
        const float4* p = reinterpret_cast<const float4*>(g_u_part);
        float4 a = p[t];
        const float4 b = p[t + 256];
        const float4 c = p[t + 512];
        const float4 d = p[t + 768];
        a.x += b.x + c.x + d.x;
        a.y += b.y + c.y + d.y;
        a.z += b.z + c.z + d.z;
        a.w += b.w + c.w + d.w;
        su[t] = a;
    }
    __syncthreads();

    const int warp  = t >> 5;
    const int lane  = t & 31;
    const int nwarp = K2_GRID * 16;           // total warps in grid

    for (int row = blockIdx.x * 16 + warp; row < L_DIM * B_DIM; row += nwarp) {
        const float4* rp = reinterpret_cast<const float4*>(hs) + (size_t)row * (H_DIM / 4);

        float acc = 0.f;
        #pragma unroll
        for (int j = 0; j < 8; j++) {
            const int idx = lane + j * 32;
            const float4 x = __ldcs(rp + idx);    // streaming, evict-first
            const float4 u = su[idx];
            acc += x.x * u.x + x.y * u.y + x.z * u.z + x.w * u.w;
        }
        #pragma unroll
        for (int o = 16; o; o >>= 1)
            acc += __shfl_xor_sync(0xffffffffu, acc, o);

        if (lane == 0) {
            const int l = row >> 6;               // row / B
            const int b = row & 63;               // row % B
            g_attn[b * L_DIM + l] = acc;
        }
    }
}

// ---------------------------------------------------------------------------
// K3: out[b, 0, l] = softmax_l(attn[b, l]).  One block per batch, 512 threads.
// ---------------------------------------------------------------------------
__global__ void __launch_bounds__(512) softmax_kernel(float* __restrict__ out) {
    __shared__ float sm[16];
    const int b = blockIdx.x;
    const int t = threadIdx.x;                // 0..511
    const int lane = t & 31, w = t >> 5;

    const float a = g_attn[b * L_DIM + t];

    float m = a;
    #pragma unroll
    for (int o = 16; o; o >>= 1) m = fmaxf(m, __shfl_xor_sync(0xffffffffu, m, o));
    if (lane == 0) sm[w] = m;
    __syncthreads();
    float M = sm[0];
    #pragma unroll
    for (int i = 1; i < 16; i++) M = fmaxf(M, sm[i]);
    __syncthreads();

    const float e = expf(a - M);

    float s = e;
    #pragma unroll
    for (int o = 16; o; o >>= 1) s += __shfl_xor_sync(0xffffffffu, s, o);
    if (lane == 0) sm[w] = s;
    __syncthreads();
    float S = sm[0];
    #pragma unroll
    for (int i = 1; i < 16; i++) S += sm[i];

    out[b * L_DIM + t] = e / S;
}

// ---------------------------------------------------------------------------
// Inputs (metadata order): hidden, hs_encoder, W_att, b_att, vector
// hidden / b_att / Wh are mathematically dead (softmax shift invariance).
// ---------------------------------------------------------------------------
extern "C" void kernel_launch(void* const* d_in, const int* in_sizes, int n_in,
                              void* d_out, int out_size) {
    const float* hs  = (const float*)d_in[1];   // (512, 64, 1024)
    const float* W   = (const float*)d_in[2];   // (1024, 2048)
    const float* vec = (const float*)d_in[4];   // (1024, 1)
    float* out = (float*)d_out;                 // (64, 1, 512)

    dim3 g1(H_DIM / 32, 4);
    compute_u_kernel<<<g1, 1024>>>(W, vec);
    dot_kernel<<<K2_GRID, 512>>>(hs);
    softmax_kernel<<<B_DIM, 512>>>(out);
}